// round 11
// baseline (speedup 1.0000x reference)
#include <cuda_runtime.h>
#include <math.h>

#define TWO_PI_F 6.28318530717958647692f
#define NEG2LOG2E 2.885390081777926814f   /* 2*log2(e) */

__device__ __forceinline__ float sqrt_approx(float x) {
    float r; asm("sqrt.approx.f32 %0, %1;" : "=f"(r) : "f"(x)); return r;
}
__device__ __forceinline__ float rcp_approx(float x) {
    float r; asm("rcp.approx.f32 %0, %1;" : "=f"(r) : "f"(x)); return r;
}
__device__ __forceinline__ float ex2_approx(float x) {
    float r; asm("ex2.approx.f32 %0, %1;" : "=f"(r) : "f"(x)); return r;
}

// ---------------------------------------------------------------------------
// One Haskell layer step. A = {dm, gammk, xka^2, xkb^2},
// B = {rho, 1/rho, -2*log2e*dm, a_layer}.
// PM: 0 = general; 1 = P evanescent for every point in the warp (wv2 > ka2 for
// all layers, strictly); 2 = P and Q evanescent (also wv2 > kb2 strictly).
// NORM: normalize this step (every 2nd layer; recursion is linear in e).
// cmax: max phase velocity in this block (PM=0 only: a_l > cmax => whole
// block P-evanescent at this layer, warp-uniform branch).
// ---------------------------------------------------------------------------
template<int PM, bool NORM>
__device__ __forceinline__ void layer_step(
    float4 A, float4 B, float wv2, float tt, float cmax,
    float& e0, float& e1, float& e2, float& e3, float& e4)
{
    const float dm = A.x;
    const float gk = A.y;

    const float ra2 = wv2 - A.z;
    const float rb2 = wv2 - A.w;
    const float ra  = sqrt_approx(fabsf(ra2));
    const float rb  = sqrt_approx(fabsf(rb2));

    const float argP = ra * B.z;            // -2*log2e * p
    const float argQ = rb * B.z;            // -2*log2e * q
    const float facP = ex2_approx(argP);    // exp(-2p)
    const float facQ = ex2_approx(argQ);    // exp(-2q)
    const float ceP  = fmaf(0.5f, facP, 0.5f);
    const float seP  = fmaf(-0.5f, facP, 0.5f);
    const float ceQ  = fmaf(0.5f, facQ, 0.5f);
    const float seQ  = fmaf(-0.5f, facQ, 0.5f);
    const float rra  = rcp_approx(ra);
    const float rrb  = rcp_approx(rb);

    // ---- P branch ----
    float cosp, w, x, fselP;
    if (PM >= 1 || B.w > cmax) {
        // strictly evanescent: no trig, no selects, no eq-guard
        cosp  = ceP;
        fselP = argP;
        w     = seP * rra;
        x     = ra * seP;
    } else {
        const float p = ra * dm;
        float sp, cp_;
        __sincosf(p, &sp, &cp_);
        const bool lt = ra2 < 0.0f;
        cosp  = lt ? cp_ : ceP;
        fselP = lt ? 0.0f : argP;
        const float num = lt ? sp : seP;
        w = (ra2 != 0.0f) ? num * rra : dm;
        x = ra * (lt ? -sp : seP);
    }

    // ---- Q branch ----
    float cosq, y, z, fselQ;
    if (PM == 2) {
        cosq  = ceQ;
        fselQ = argQ;
        y     = seQ * rrb;
        z     = rb * seQ;
    } else {
        const float q = rb * dm;
        float sq, cq_;
        __sincosf(q, &sq, &cq_);
        const bool ltB = rb2 < 0.0f;
        cosq  = ltB ? cq_ : ceQ;
        fselQ = ltB ? 0.0f : argQ;
        const float ynum = ltB ? sq : seQ;
        y = (rb2 != 0.0f) ? ynum * rrb : dm;
        z = rb * (ltB ? -sq : seQ);
    }

    // a0 = exp(-(pex+sex)) = 2^(0.5*(fselP+fselQ))
    const float a0 = ex2_approx(0.5f * (fselP + fselQ));

    const float cpcq = cosp * cosq;
    const float cpy  = cosp * y;
    const float cpz  = cosp * z;
    const float cqw  = cosq * w;
    const float cqx  = cosq * x;
    const float xy   = x * y;
    const float xz   = x * z;
    const float wy   = w * y;
    const float wz   = w * z;

    // ---- _dnka (shared subexpressions made explicit) ----
    const float gam   = gk * wv2;
    const float gamm1 = gam - 1.0f;
    const float twgm1 = gam + gamm1;
    const float gmgmk = gam * gk;
    const float gmgm1 = gam * gamm1;
    const float gm1sq = gamm1 * gamm1;
    const float rho   = B.x;
    const float irho  = B.y;
    const float rho2  = rho * rho;
    const float irho2 = irho * irho;
    const float a0pq  = a0 - cpcq;

    const float wvwy = wv2 * wy;       // feeds c00, c02, c04
    const float gw   = gm1sq * wy;     // feeds c40, c42
    const float gxz  = gmgmk * xz;     // feeds c00, c40, c42

    const float c00 = cpcq - 2.0f * gmgm1 * a0pq - gxz - gm1sq * wvwy;
    const float c01 = (wv2 * cpy - cqx) * irho;
    const float c02 = -(twgm1 * a0pq + gk * xz + gamm1 * wvwy) * irho;
    const float c03 = (cpz - wv2 * cqw) * irho;
    const float c04 = -(2.0f * wv2 * a0pq + xz + wv2 * wvwy) * irho2;
    const float c10 = (gmgmk * cpz - gm1sq * cqw) * rho;
    const float c11 = cpcq;
    const float c12 = gk * cpz - gamm1 * cqw;
    const float c13 = -wz;
    const float c30 = (gm1sq * cpy - gmgmk * cqx) * rho;
    const float c31 = -xy;
    const float c32 = gamm1 * cpy - gk * cqx;
    const float c40 = -(2.0f * gmgmk * gm1sq * a0pq + gmgmk * gxz + gm1sq * gw) * rho2;
    const float c42 = -(gk * gamm1 * twgm1 * a0pq + gk * gxz + gamm1 * gw) * rho;
    const float c22 = a0 + 2.0f * (cpcq - c00);

    // e2t folds tt = -2*wvno2 into e2, replacing c20/c21/c23/c24 entirely.
    const float e2t = tt * e2;

    const float ee0 = e0 * c00 + e1 * c10 + e2t * c42 + e3 * c30 + e4 * c40;
    const float ee1 = e0 * c01 + e1 * c11 + e2t * c32 + e3 * c31 + e4 * c30;
    const float ee2 = e0 * c02 + e1 * c12 + e2  * c22 + e3 * c32 + e4 * c42;
    const float ee3 = e0 * c03 + e1 * c13 + e2t * c12 + e3 * c11 + e4 * c10;
    const float ee4 = e0 * c04 + e1 * c03 + e2t * c02 + e3 * c01 + e4 * c00;

    if (NORM) {
        float t1 = fmaxf(fabsf(ee0),
                   fmaxf(fabsf(ee1),
                   fmaxf(fabsf(ee2),
                   fmaxf(fabsf(ee3), fabsf(ee4)))));
        if (t1 < 1e-30f) t1 = 1.0f;
        const float s = rcp_approx(t1);
        e0 = ee0 * s; e1 = ee1 * s; e2 = ee2 * s; e3 = ee3 * s; e4 = ee4 * s;
    } else {
        e0 = ee0; e1 = ee1; e2 = ee2; e3 = ee3; e4 = ee4;
    }
}

template<int PM>
__device__ __forceinline__ float dltar4_point(
    float wv2, int L, float cmax,
    const float4* __restrict__ sA, const float4* __restrict__ sB)
{
    float e0, e1, e2, e3, e4;
    {
        const float4 A = sA[L - 1];
        const float4 B = sB[L - 1];
        const float ra = sqrt_approx(fabsf(wv2 - A.z));
        const float rb = sqrt_approx(fabsf(wv2 - A.w));
        const float gam = A.y * wv2;
        const float gamm1 = gam - 1.0f;
        const float r = B.x;
        const float rarb = ra * rb;
        e0 = r * r * (gamm1 * gamm1 - gam * A.y * rarb);
        e1 = -r * ra;
        e2 = r * (gamm1 - A.y * rarb);
        e3 = r * rb;
        e4 = wv2 - rarb;
    }
    const float tt = -2.0f * wv2;

    // il = L-2 .. 0, normalization on even il (final step il==0 normalizes).
    const float4* Ap = sA + (L - 2);
    const float4* Bp = sB + (L - 2);
    int il = L - 2;
#pragma unroll 1
    for (; il > 0; il -= 2) {
        layer_step<PM, true >(Ap[0],  Bp[0],  wv2, tt, cmax, e0, e1, e2, e3, e4);
        layer_step<PM, false>(Ap[-1], Bp[-1], wv2, tt, cmax, e0, e1, e2, e3, e4);
        Ap -= 2; Bp -= 2;
    }
    layer_step<PM, true>(sA[0], sB[0], wv2, tt, cmax, e0, e1, e2, e3, e4);
    return e0;
}

// ---------------------------------------------------------------------------
// One block per (m, p); 128 threads over 401 items (NC grid dets + e00 det).
// Uniform pass loop so each warp can vote (__all_sync) and dispatch into an
// evanescent-specialized chain when its entire 32-c range qualifies.
// ---------------------------------------------------------------------------
__global__ void __launch_bounds__(128, 8)
forward_kernel(const float* __restrict__ vlist, const float* __restrict__ tlist,
               const float* __restrict__ dlay, const float* __restrict__ blay,
               const float* __restrict__ Clist, float* __restrict__ out,
               int M, int P, int L, int NC)
{
    __shared__ float  sIC[1024];
    __shared__ float4 sA[64];   // dm, gk, ka2, kb2
    __shared__ float4 sB[64];   // rho, irho, -2log2e*dm, a_l
    __shared__ float  sbv[64];
    __shared__ float  red_mn[4], red_mx[4], sh_e00;
    __shared__ int    sCmaxBits, sKa2MaxBits, sKb2MaxBits;

    const int m   = blockIdx.y;
    const int p   = blockIdx.x;
    const int tid = threadIdx.x;

    if (tid == 0) { sCmaxBits = 0; sKa2MaxBits = 0; sKb2MaxBits = 0; }
    __syncthreads();

    const float om  = fmaxf(TWO_PI_F / tlist[m * P + p], 1e-4f);
    const float iom = 1.0f / om;
    const float vml = vlist[m * P + p];

    for (int l = tid; l < L; l += blockDim.x) {
        const float bv = blay[m * L + l];
        const float av = 0.9409f + bv * (2.0947f + bv * (-0.8206f + bv * (0.2683f + bv * (-0.0251f))));
        const float rv = av * (1.6612f + av * (-0.4721f + av * (0.0671f + av * (-0.0043f + av * 0.000106f))));
        const float xka = om / av;
        const float xkb = om / bv;
        const float t   = bv * iom;
        const float dm  = dlay[m * L + l];
        const float ka2 = xka * xka;
        const float kb2 = xkb * xkb;
        sA[l] = make_float4(dm, 2.0f * t * t, ka2, kb2);
        sB[l] = make_float4(rv, 1.0f / rv, -NEG2LOG2E * dm, av);
        sbv[l] = bv;
        atomicMax(&sKa2MaxBits, __float_as_int(ka2));
        atomicMax(&sKb2MaxBits, __float_as_int(kb2));
    }
    {
        float lmax = vml;
        for (int k = tid; k < NC; k += blockDim.x) {
            const float c = Clist[k];
            sIC[k] = 1.0f / c;
            lmax = fmaxf(lmax, c);
        }
        atomicMax(&sCmaxBits, __float_as_int(lmax));
    }
    __syncthreads();

    const float cmax   = __int_as_float(sCmaxBits);
    const float ka2max = __int_as_float(sKa2MaxBits);
    const float kb2max = __int_as_float(sKb2MaxBits);
    const float wve    = om / vml;

    float mn =  3.4e38f;
    float mx = -3.4e38f;
    const unsigned full = 0xffffffffu;

    for (int k0 = 0; k0 <= NC; k0 += 128) {
        const int k = k0 + tid;
        if (__all_sync(full, k > NC)) break;          // warp-uniform exit
        const float wv  = (k < NC) ? (om * sIC[k]) : wve;  // k>NC lanes clamp
        const float wv2 = wv * wv;

        // Warp votes: entire 32-lane c-range strictly evanescent?
        const bool pEv = __all_sync(full, wv2 > ka2max);
        const bool qEv = pEv && __all_sync(full, wv2 > kb2max);

        float det;
        if (qEv)      det = dltar4_point<2>(wv2, L, cmax, sA, sB);
        else if (pEv) det = dltar4_point<1>(wv2, L, cmax, sA, sB);
        else          det = dltar4_point<0>(wv2, L, cmax, sA, sB);

        if (k < NC) {
            mn = fminf(mn, det);
            mx = fmaxf(mx, det);
        } else if (k == NC) {
            sh_e00 = det;
        }
    }

#pragma unroll
    for (int o = 16; o > 0; o >>= 1) {
        mn = fminf(mn, __shfl_xor_sync(full, mn, o));
        mx = fmaxf(mx, __shfl_xor_sync(full, mx, o));
    }
    if ((tid & 31) == 0) {
        red_mn[tid >> 5] = mn;
        red_mx[tid >> 5] = mx;
    }
    __syncthreads();

    if (tid == 0) {
        mn = fminf(fminf(red_mn[0], red_mn[1]), fminf(red_mn[2], red_mn[3]));
        mx = fmaxf(fmaxf(red_mx[0], red_mx[1]), fmaxf(red_mx[2], red_mx[3]));
        const float rng = mx - mn;
        const float val = sh_e00 / rng;
        // |0.1^|val| - 1| = 1 - 10^(-|val|)
        const float contrib = (1.0f - exp10f(-fabsf(val))) / (float)P;
        atomicAdd(&out[m], contrib);
    }

    // Regularizer (DAMP_HORIZONTAL = 0): once per m, by the p==0 block.
    if (p == 0 && tid == 32) {
        float s = 0.0f;
        for (int i = 0; i < L; ++i) {
            float v;
            if (i == 0)          v = sbv[0] - sbv[1];
            else if (i == L - 1) v = sbv[L - 1] - sbv[L - 2];
            else                 v = 2.0f * sbv[i] - sbv[i - 1] - sbv[i + 1];
            s += fabsf(v);
        }
        atomicAdd(&out[m], s / (float)L);
    }
}

extern "C" void kernel_launch(void* const* d_in, const int* in_sizes, int n_in,
                              void* d_out, int out_size)
{
    const float* vlist = (const float*)d_in[0];
    const float* tlist = (const float*)d_in[1];
    const float* dlay  = (const float*)d_in[2];
    const float* blay  = (const float*)d_in[3];
    const float* Clist = (const float*)d_in[4];
    float* out = (float*)d_out;

    const int M  = out_size;          // 64
    const int P  = in_sizes[0] / M;   // 100
    const int L  = in_sizes[3] / M;   // 32
    const int NC = in_sizes[4];       // 400

    cudaMemsetAsync(out, 0, (size_t)M * sizeof(float));

    dim3 grid(P, M);
    forward_kernel<<<grid, 128>>>(vlist, tlist, dlay, blay, Clist, out,
                                  M, P, L, NC);
}

// round 12
// speedup vs baseline: 1.0590x; 1.0590x over previous
#include <cuda_runtime.h>
#include <math.h>

#define TWO_PI_F 6.28318530717958647692f
#define NEG2LOG2E 2.885390081777926814f   /* 2*log2(e) */

__device__ __forceinline__ float sqrt_approx(float x) {
    float r; asm("sqrt.approx.f32 %0, %1;" : "=f"(r) : "f"(x)); return r;
}
__device__ __forceinline__ float rcp_approx(float x) {
    float r; asm("rcp.approx.f32 %0, %1;" : "=f"(r) : "f"(x)); return r;
}
__device__ __forceinline__ float ex2_approx(float x) {
    float r; asm("ex2.approx.f32 %0, %1;" : "=f"(r) : "f"(x)); return r;
}

// ---------------------------------------------------------------------------
// One Haskell layer step in the rho-similarity basis (e~ = e * diag(rho^s),
// s = (0,1,1,1,2)):  CA = D*CAhat*D^-1 with CAhat rho-free, so all rho
// multiplies vanish; entering this layer costs 4 ratio muls (rr, rr^2).
// Intermediate normalizations are arbitrary scalings (they telescope out of
// e0/max|e|), so normalizing in the hat basis is exact algebra.
// A = {dm, gammk, xka^2, xkb^2}; B = {rr, rr^2, -2*log2e*dm, b_layer}.
// Per-layer warp votes skip trig+selects when the whole warp is strictly
// evanescent in P and/or Q.
// ---------------------------------------------------------------------------
template<bool NORM>
__device__ __forceinline__ void layer_step(
    float4 A, float4 B, float wv2, float tt,
    float& e0, float& e1, float& e2, float& e3, float& e4)
{
    const unsigned full = 0xffffffffu;
    const float dm = A.x;
    const float gk = A.y;

    // basis change from previous layer's rho to this layer's rho
    e1 *= B.x; e2 *= B.x; e3 *= B.x; e4 *= B.y;

    const float ra2 = wv2 - A.z;
    const float rb2 = wv2 - A.w;
    const float ra  = sqrt_approx(fabsf(ra2));
    const float rb  = sqrt_approx(fabsf(rb2));

    const float argP = ra * B.z;            // -2*log2e * p
    const float argQ = rb * B.z;            // -2*log2e * q
    const float facP = ex2_approx(argP);    // exp(-2p)
    const float facQ = ex2_approx(argQ);    // exp(-2q)
    const float ceP  = fmaf(0.5f, facP, 0.5f);
    const float seP  = fmaf(-0.5f, facP, 0.5f);
    const float ceQ  = fmaf(0.5f, facQ, 0.5f);
    const float seQ  = fmaf(-0.5f, facQ, 0.5f);
    const float rra  = rcp_approx(ra);
    const float rrb  = rcp_approx(rb);

    // ---- P branch: warp-uniform fast path when all lanes strictly evan ----
    float cosp, w, x, fselP;
    if (__any_sync(full, ra2 <= 0.0f)) {
        const float p = ra * dm;
        float sp, cp_;
        __sincosf(p, &sp, &cp_);
        const bool lt = ra2 < 0.0f;
        cosp  = lt ? cp_ : ceP;
        fselP = lt ? 0.0f : argP;
        const float num = lt ? sp : seP;
        w = (ra2 != 0.0f) ? num * rra : dm;
        x = ra * (lt ? -sp : seP);
    } else {
        cosp  = ceP;
        fselP = argP;
        w     = seP * rra;
        x     = ra * seP;
    }

    // ---- Q branch ----
    float cosq, y, z, fselQ;
    if (__any_sync(full, rb2 <= 0.0f)) {
        const float q = rb * dm;
        float sq, cq_;
        __sincosf(q, &sq, &cq_);
        const bool ltB = rb2 < 0.0f;
        cosq  = ltB ? cq_ : ceQ;
        fselQ = ltB ? 0.0f : argQ;
        const float ynum = ltB ? sq : seQ;
        y = (rb2 != 0.0f) ? ynum * rrb : dm;
        z = rb * (ltB ? -sq : seQ);
    } else {
        cosq  = ceQ;
        fselQ = argQ;
        y     = seQ * rrb;
        z     = rb * seQ;
    }

    // a0 = exp(-(pex+sex)) = 2^(0.5*(fselP+fselQ))
    const float a0 = ex2_approx(0.5f * (fselP + fselQ));

    const float cpcq = cosp * cosq;
    const float cpy  = cosp * y;
    const float cpz  = cosp * z;
    const float cqw  = cosq * w;
    const float cqx  = cosq * x;
    const float xy   = x * y;
    const float xz   = x * z;
    const float wy   = w * y;
    const float wz   = w * z;

    // ---- _dnka, hat basis (rho-free) ----
    const float gam   = gk * wv2;
    const float gamm1 = gam - 1.0f;
    const float twgm1 = gam + gamm1;
    const float gmgmk = gam * gk;
    const float gmgm1 = gam * gamm1;
    const float gm1sq = gamm1 * gamm1;
    const float a0pq  = a0 - cpcq;

    const float wvwy = wv2 * wy;
    const float gw   = gm1sq * wy;
    const float gxz  = gmgmk * xz;

    const float c00 = cpcq - 2.0f * gmgm1 * a0pq - gxz - gm1sq * wvwy;
    const float c01 = wv2 * cpy - cqx;
    const float c02 = -(twgm1 * a0pq + gk * xz + gamm1 * wvwy);
    const float c03 = cpz - wv2 * cqw;
    const float c04 = -(2.0f * wv2 * a0pq + xz + wv2 * wvwy);
    const float c10 = gmgmk * cpz - gm1sq * cqw;
    const float c11 = cpcq;
    const float c12 = gk * cpz - gamm1 * cqw;
    const float c13 = -wz;
    const float c30 = gm1sq * cpy - gmgmk * cqx;
    const float c31 = -xy;
    const float c32 = gamm1 * cpy - gk * cqx;
    const float c40 = -(2.0f * gmgmk * gm1sq * a0pq + gmgmk * gxz + gm1sq * gw);
    const float c42 = -(gk * gamm1 * twgm1 * a0pq + gk * gxz + gamm1 * gw);
    const float c22 = a0 + 2.0f * (cpcq - c00);

    // e2t folds tt = -2*wvno2 into e2, replacing c20/c21/c23/c24 entirely.
    const float e2t = tt * e2;

    const float ee0 = e0 * c00 + e1 * c10 + e2t * c42 + e3 * c30 + e4 * c40;
    const float ee1 = e0 * c01 + e1 * c11 + e2t * c32 + e3 * c31 + e4 * c30;
    const float ee2 = e0 * c02 + e1 * c12 + e2  * c22 + e3 * c32 + e4 * c42;
    const float ee3 = e0 * c03 + e1 * c13 + e2t * c12 + e3 * c11 + e4 * c10;
    const float ee4 = e0 * c04 + e1 * c03 + e2t * c02 + e3 * c01 + e4 * c00;

    if (NORM) {
        // overflow-control scaling only (value cancels in the telescoping)
        float t1 = fmaxf(fabsf(ee0),
                   fmaxf(fabsf(ee1),
                   fmaxf(fabsf(ee2),
                   fmaxf(fabsf(ee3), fabsf(ee4)))));
        t1 = fmaxf(t1, 1e-30f);
        const float s = rcp_approx(t1);
        e0 = ee0 * s; e1 = ee1 * s; e2 = ee2 * s; e3 = ee3 * s; e4 = ee4 * s;
    } else {
        e0 = ee0; e1 = ee1; e2 = ee2; e3 = ee3; e4 = ee4;
    }
}

__device__ __forceinline__ float dltar4_point(
    float wv2, int L, float ir0,
    const float4* __restrict__ sA, const float4* __restrict__ sB)
{
    float e0, e1, e2, e3, e4;
    {
        // Halfspace init, hat basis of layer L-1; the overall r^2 factor is an
        // arbitrary scale and is dropped (it telescopes out).
        const float4 A = sA[L - 1];
        const float ra = sqrt_approx(fabsf(wv2 - A.z));
        const float rb = sqrt_approx(fabsf(wv2 - A.w));
        const float gam = A.y * wv2;
        const float gamm1 = gam - 1.0f;
        const float rarb = ra * rb;
        e0 = gamm1 * gamm1 - gam * A.y * rarb;
        e1 = -ra;
        e2 = gamm1 - A.y * rarb;
        e3 = rb;
        e4 = wv2 - rarb;
    }
    const float tt = -2.0f * wv2;

    // il = L-2 .. 1 in pairs (norm on the even one); il = 0 handled last.
    const float4* Ap = sA + (L - 2);
    const float4* Bp = sB + (L - 2);
#pragma unroll 1
    for (int il = L - 2; il > 0; il -= 2) {
        layer_step<true >(Ap[0],  Bp[0],  wv2, tt, e0, e1, e2, e3, e4);
        layer_step<false>(Ap[-1], Bp[-1], wv2, tt, e0, e1, e2, e3, e4);
        Ap -= 2; Bp -= 2;
    }
    layer_step<false>(sA[0], sB[0], wv2, tt, e0, e1, e2, e3, e4);

    // Convert back to the true basis (D_0^-1) and apply the reference's final
    // normalization; only e0/t1 is needed.
    e1 *= ir0; e2 *= ir0; e3 *= ir0; e4 *= ir0 * ir0;
    float t1 = fmaxf(fabsf(e0),
               fmaxf(fabsf(e1),
               fmaxf(fabsf(e2),
               fmaxf(fabsf(e3), fabsf(e4)))));
    if (t1 < 1e-30f) t1 = 1.0f;
    return e0 * rcp_approx(t1);
}

// ---------------------------------------------------------------------------
// One block per (m, p); 128 threads over 401 items (NC grid dets + e00 det).
// Warp-uniform pass break + clamped tail lanes: every executing warp has all
// 32 lanes active (full-mask votes legal); 13 warp-passes per block.
// ---------------------------------------------------------------------------
__global__ void __launch_bounds__(128, 8)
forward_kernel(const float* __restrict__ vlist, const float* __restrict__ tlist,
               const float* __restrict__ dlay, const float* __restrict__ blay,
               const float* __restrict__ Clist, float* __restrict__ out,
               int M, int P, int L, int NC)
{
    __shared__ float  sIC[1024];
    __shared__ float4 sA[64];   // dm, gk, ka2, kb2
    __shared__ float4 sB[64];   // rr, rr^2, -2log2e*dm, b_l
    __shared__ float  red_mn[4], red_mx[4], sh_e00, sIr0;

    const int m   = blockIdx.y;
    const int p   = blockIdx.x;
    const int tid = threadIdx.x;

    const float om  = fmaxf(TWO_PI_F / tlist[m * P + p], 1e-4f);
    const float iom = 1.0f / om;
    const float vml = vlist[m * P + p];

    for (int l = tid; l < L; l += blockDim.x) {
        const float bv = blay[m * L + l];
        const float av = 0.9409f + bv * (2.0947f + bv * (-0.8206f + bv * (0.2683f + bv * (-0.0251f))));
        const float rv = av * (1.6612f + av * (-0.4721f + av * (0.0671f + av * (-0.0043f + av * 0.000106f))));
        // rho of layer l+1 (for the basis ratio); dummy for l == L-1
        float rn = rv;
        if (l < L - 1) {
            const float bv2 = blay[m * L + l + 1];
            const float av2 = 0.9409f + bv2 * (2.0947f + bv2 * (-0.8206f + bv2 * (0.2683f + bv2 * (-0.0251f))));
            rn = av2 * (1.6612f + av2 * (-0.4721f + av2 * (0.0671f + av2 * (-0.0043f + av2 * 0.000106f))));
        }
        const float rr  = rv / rn;
        const float xka = om / av;
        const float xkb = om / bv;
        const float t   = bv * iom;
        const float dm  = dlay[m * L + l];
        sA[l] = make_float4(dm, 2.0f * t * t, xka * xka, xkb * xkb);
        sB[l] = make_float4(rr, rr * rr, -NEG2LOG2E * dm, bv);
        if (l == 0) sIr0 = 1.0f / rv;
    }
    for (int k = tid; k < NC; k += blockDim.x) sIC[k] = 1.0f / Clist[k];
    __syncthreads();

    const float ir0 = sIr0;
    const float wve = om / vml;

    float mn =  3.4e38f;
    float mx = -3.4e38f;
    const unsigned full = 0xffffffffu;

    for (int k0 = 0; k0 <= NC; k0 += 128) {
        const int kw = k0 + (tid & ~31);
        if (kw > NC) break;                      // warp-uniform exit
        const int kk = k0 + tid;
        const int k  = (kk < NC) ? kk : NC;      // clamp tail lanes to e00
        const float wv = (k < NC) ? (om * sIC[k]) : wve;
        const float det = dltar4_point(wv * wv, L, ir0, sA, sB);
        if (kk < NC) {
            mn = fminf(mn, det);
            mx = fmaxf(mx, det);
        } else if (kk == NC) {
            sh_e00 = det;
        }
    }

#pragma unroll
    for (int o = 16; o > 0; o >>= 1) {
        mn = fminf(mn, __shfl_xor_sync(full, mn, o));
        mx = fmaxf(mx, __shfl_xor_sync(full, mx, o));
    }
    if ((tid & 31) == 0) {
        red_mn[tid >> 5] = mn;
        red_mx[tid >> 5] = mx;
    }
    __syncthreads();

    if (tid == 0) {
        mn = fminf(fminf(red_mn[0], red_mn[1]), fminf(red_mn[2], red_mn[3]));
        mx = fmaxf(fmaxf(red_mx[0], red_mx[1]), fmaxf(red_mx[2], red_mx[3]));
        const float rng = mx - mn;
        const float val = sh_e00 / rng;
        // |0.1^|val| - 1| = 1 - 10^(-|val|)
        const float contrib = (1.0f - exp10f(-fabsf(val))) / (float)P;
        atomicAdd(&out[m], contrib);
    }

    // Regularizer (DAMP_HORIZONTAL = 0): once per m, by the p==0 block.
    if (p == 0 && tid == 32) {
        float s = 0.0f;
        for (int i = 0; i < L; ++i) {
            float v;
            if (i == 0)          v = sB[0].w - sB[1].w;
            else if (i == L - 1) v = sB[L - 1].w - sB[L - 2].w;
            else                 v = 2.0f * sB[i].w - sB[i - 1].w - sB[i + 1].w;
            s += fabsf(v);
        }
        atomicAdd(&out[m], s / (float)L);
    }
}

extern "C" void kernel_launch(void* const* d_in, const int* in_sizes, int n_in,
                              void* d_out, int out_size)
{
    const float* vlist = (const float*)d_in[0];
    const float* tlist = (const float*)d_in[1];
    const float* dlay  = (const float*)d_in[2];
    const float* blay  = (const float*)d_in[3];
    const float* Clist = (const float*)d_in[4];
    float* out = (float*)d_out;

    const int M  = out_size;          // 64
    const int P  = in_sizes[0] / M;   // 100
    const int L  = in_sizes[3] / M;   // 32
    const int NC = in_sizes[4];       // 400

    cudaMemsetAsync(out, 0, (size_t)M * sizeof(float));

    dim3 grid(P, M);
    forward_kernel<<<grid, 128>>>(vlist, tlist, dlay, blay, Clist, out,
                                  M, P, L, NC);
}

// round 13
// speedup vs baseline: 1.1277x; 1.0649x over previous
#include <cuda_runtime.h>
#include <math.h>

#define TWO_PI_F 6.28318530717958647692f
#define NEG2LOG2E 2.885390081777926814f   /* 2*log2(e) */

__device__ __forceinline__ float sqrt_approx(float x) {
    float r; asm("sqrt.approx.f32 %0, %1;" : "=f"(r) : "f"(x)); return r;
}
__device__ __forceinline__ float rcp_approx(float x) {
    float r; asm("rcp.approx.f32 %0, %1;" : "=f"(r) : "f"(x)); return r;
}
__device__ __forceinline__ float ex2_approx(float x) {
    float r; asm("ex2.approx.f32 %0, %1;" : "=f"(r) : "f"(x)); return r;
}

// ---------------------------------------------------------------------------
// One Haskell layer step, in TWO exact telescoping bases:
//  (a) rho-similarity basis (e~ = e*diag(rho^s), s=(0,1,1,1,2)): CAhat is
//      rho-free; entering a layer costs 4 ratio muls.
//  (b) radical-scaled P/Q vectors: P-vec (cosp,w,x) scaled by ra, Q-vec
//      (cosq,y,z) scaled by rb. All 9 products and a0 then carry a uniform
//      factor R = ra*rb, so the whole layer matrix scales by R — which
//      telescopes out of e0/max|e|. This eliminates both rcp(ra), rcp(rb)
//      and the w/x divisions:
//        w' = lt ? sinp : seP          (no division!)
//        x' = ra2 * (lt ? sinp : seP)  (same select, sign exact: ra2<0 in lt)
//        cosp' = ra * (lt ? cosp : ceP)
//      a0 is replaced by a0*R.
// The exact-equality case (wvno == xka) is absorbed by adding 1e-30f to ra2:
// only an exactly-zero ra2 is changed, and the tiny-ra limit reproduces the
// reference's w = dm behavior to the same fp32 precision the reference has.
// A = {dm, gammk, xka^2, xkb^2}; B = {rr, rr^2, -2*log2e*dm, b_layer}.
// Per-layer warp votes skip trig+selects when no lane is propagating.
// ---------------------------------------------------------------------------
template<bool NORM>
__device__ __forceinline__ void layer_step(
    float4 A, float4 B, float wv2, float tt,
    float& e0, float& e1, float& e2, float& e3, float& e4)
{
    const unsigned full = 0xffffffffu;
    const float dm = A.x;
    const float gk = A.y;

    // basis change from previous layer's rho to this layer's rho
    e1 *= B.x; e2 *= B.x; e3 *= B.x; e4 *= B.y;

    const float ra2 = (wv2 - A.z) + 1e-30f;
    const float rb2 = (wv2 - A.w) + 1e-30f;
    const float ra  = sqrt_approx(fabsf(ra2));
    const float rb  = sqrt_approx(fabsf(rb2));

    const float argP = ra * B.z;            // -2*log2e * p
    const float argQ = rb * B.z;            // -2*log2e * q
    const float facP = ex2_approx(argP);    // exp(-2p)
    const float facQ = ex2_approx(argQ);    // exp(-2q)
    const float ceP  = fmaf(0.5f, facP, 0.5f);
    const float seP  = fmaf(-0.5f, facP, 0.5f);
    const float ceQ  = fmaf(0.5f, facQ, 0.5f);
    const float seQ  = fmaf(-0.5f, facQ, 0.5f);

    // ---- P side (scaled by ra) ----
    float cpS, wS, xS, fselP;
    if (__any_sync(full, ra2 < 0.0f)) {
        const float p = ra * dm;
        float sp, cp_;
        __sincosf(p, &sp, &cp_);
        const bool lt = ra2 < 0.0f;
        const float sel = lt ? sp : seP;
        wS    = sel;
        xS    = ra2 * sel;              // lt: ra2<0 gives -ra^2*sp exactly
        cpS   = ra * (lt ? cp_ : ceP);
        fselP = lt ? 0.0f : argP;
    } else {
        wS    = seP;
        xS    = ra2 * seP;
        cpS   = ra * ceP;
        fselP = argP;
    }

    // ---- Q side (scaled by rb) ----
    float cqS, yS, zS, fselQ;
    if (__any_sync(full, rb2 < 0.0f)) {
        const float q = rb * dm;
        float sq, cq_;
        __sincosf(q, &sq, &cq_);
        const bool lt = rb2 < 0.0f;
        const float sel = lt ? sq : seQ;
        yS    = sel;
        zS    = rb2 * sel;
        cqS   = rb * (lt ? cq_ : ceQ);
        fselQ = lt ? 0.0f : argQ;
    } else {
        yS    = seQ;
        zS    = rb2 * seQ;
        cqS   = rb * ceQ;
        fselQ = argQ;
    }

    // a0 in the scaled basis: a0 * R, R = ra*rb
    const float a0R = ex2_approx(0.5f * (fselP + fselQ)) * (ra * rb);

    const float cpcq = cpS * cqS;
    const float cpy  = cpS * yS;
    const float cpz  = cpS * zS;
    const float cqw  = cqS * wS;
    const float cqx  = cqS * xS;
    const float xy   = xS * yS;
    const float xz   = xS * zS;
    const float wy   = wS * yS;
    const float wz   = wS * zS;

    // ---- _dnka, hat basis (rho-free), entries scaled uniformly by R ----
    const float gam   = gk * wv2;
    const float gamm1 = gam - 1.0f;
    const float twgm1 = gam + gamm1;
    const float gmgmk = gam * gk;
    const float gmgm1 = gam * gamm1;
    const float gm1sq = gamm1 * gamm1;
    const float a0pq  = a0R - cpcq;

    const float wvwy = wv2 * wy;
    const float gw   = gm1sq * wy;
    const float gxz  = gmgmk * xz;

    const float c00 = cpcq - 2.0f * gmgm1 * a0pq - gxz - gm1sq * wvwy;
    const float c01 = wv2 * cpy - cqx;
    const float c02 = -(twgm1 * a0pq + gk * xz + gamm1 * wvwy);
    const float c03 = cpz - wv2 * cqw;
    const float c04 = -(2.0f * wv2 * a0pq + xz + wv2 * wvwy);
    const float c10 = gmgmk * cpz - gm1sq * cqw;
    const float c11 = cpcq;
    const float c12 = gk * cpz - gamm1 * cqw;
    const float c13 = -wz;
    const float c30 = gm1sq * cpy - gmgmk * cqx;
    const float c31 = -xy;
    const float c32 = gamm1 * cpy - gk * cqx;
    const float c40 = -(2.0f * gmgmk * gm1sq * a0pq + gmgmk * gxz + gm1sq * gw);
    const float c42 = -(gk * gamm1 * twgm1 * a0pq + gk * gxz + gamm1 * gw);
    const float c22 = a0R + 2.0f * (cpcq - c00);

    // e2t folds tt = -2*wvno2 into e2, replacing c20/c21/c23/c24 entirely.
    const float e2t = tt * e2;

    const float ee0 = e0 * c00 + e1 * c10 + e2t * c42 + e3 * c30 + e4 * c40;
    const float ee1 = e0 * c01 + e1 * c11 + e2t * c32 + e3 * c31 + e4 * c30;
    const float ee2 = e0 * c02 + e1 * c12 + e2  * c22 + e3 * c32 + e4 * c42;
    const float ee3 = e0 * c03 + e1 * c13 + e2t * c12 + e3 * c11 + e4 * c10;
    const float ee4 = e0 * c04 + e1 * c03 + e2t * c02 + e3 * c01 + e4 * c00;

    if (NORM) {
        // overflow-control scaling only (value cancels in the telescoping)
        float t1 = fmaxf(fabsf(ee0),
                   fmaxf(fabsf(ee1),
                   fmaxf(fabsf(ee2),
                   fmaxf(fabsf(ee3), fabsf(ee4)))));
        t1 = fmaxf(t1, 1e-30f);
        const float s = rcp_approx(t1);
        e0 = ee0 * s; e1 = ee1 * s; e2 = ee2 * s; e3 = ee3 * s; e4 = ee4 * s;
    } else {
        e0 = ee0; e1 = ee1; e2 = ee2; e3 = ee3; e4 = ee4;
    }
}

__device__ __forceinline__ float dltar4_point(
    float wv2, int L, float ir0,
    const float4* __restrict__ sA, const float4* __restrict__ sB)
{
    float e0, e1, e2, e3, e4;
    {
        // Halfspace init, hat basis of layer L-1 (overall r^2 scale dropped).
        const float4 A = sA[L - 1];
        const float ra = sqrt_approx(fabsf(wv2 - A.z));
        const float rb = sqrt_approx(fabsf(wv2 - A.w));
        const float gam = A.y * wv2;
        const float gamm1 = gam - 1.0f;
        const float rarb = ra * rb;
        e0 = gamm1 * gamm1 - gam * A.y * rarb;
        e1 = -ra;
        e2 = gamm1 - A.y * rarb;
        e3 = rb;
        e4 = wv2 - rarb;
    }
    const float tt = -2.0f * wv2;

    // il = L-2 .. 1 in pairs (norm on the even one); il = 0 handled last.
    const float4* Ap = sA + (L - 2);
    const float4* Bp = sB + (L - 2);
#pragma unroll 1
    for (int il = L - 2; il > 0; il -= 2) {
        layer_step<true >(Ap[0],  Bp[0],  wv2, tt, e0, e1, e2, e3, e4);
        layer_step<false>(Ap[-1], Bp[-1], wv2, tt, e0, e1, e2, e3, e4);
        Ap -= 2; Bp -= 2;
    }
    layer_step<false>(sA[0], sB[0], wv2, tt, e0, e1, e2, e3, e4);

    // Convert back to the true basis (D_0^-1) and apply the reference's final
    // normalization; only e0/t1 is needed.
    e1 *= ir0; e2 *= ir0; e3 *= ir0; e4 *= ir0 * ir0;
    float t1 = fmaxf(fabsf(e0),
               fmaxf(fabsf(e1),
               fmaxf(fabsf(e2),
               fmaxf(fabsf(e3), fabsf(e4)))));
    if (t1 < 1e-30f) t1 = 1.0f;
    return e0 * rcp_approx(t1);
}

// ---------------------------------------------------------------------------
// One block per (m, p); 128 threads over 401 items (NC grid dets + e00 det).
// Warp-uniform pass break + clamped tail lanes: every executing warp has all
// 32 lanes active (full-mask votes legal); 13 warp-passes per block.
// ---------------------------------------------------------------------------
__global__ void __launch_bounds__(128, 8)
forward_kernel(const float* __restrict__ vlist, const float* __restrict__ tlist,
               const float* __restrict__ dlay, const float* __restrict__ blay,
               const float* __restrict__ Clist, float* __restrict__ out,
               int M, int P, int L, int NC)
{
    __shared__ float  sIC[1024];
    __shared__ float4 sA[64];   // dm, gk, ka2, kb2
    __shared__ float4 sB[64];   // rr, rr^2, -2log2e*dm, b_l
    __shared__ float  red_mn[4], red_mx[4], sh_e00, sIr0;

    const int m   = blockIdx.y;
    const int p   = blockIdx.x;
    const int tid = threadIdx.x;

    const float om  = fmaxf(TWO_PI_F / tlist[m * P + p], 1e-4f);
    const float iom = 1.0f / om;
    const float vml = vlist[m * P + p];

    for (int l = tid; l < L; l += blockDim.x) {
        const float bv = blay[m * L + l];
        const float av = 0.9409f + bv * (2.0947f + bv * (-0.8206f + bv * (0.2683f + bv * (-0.0251f))));
        const float rv = av * (1.6612f + av * (-0.4721f + av * (0.0671f + av * (-0.0043f + av * 0.000106f))));
        // rho of layer l+1 (for the basis ratio); dummy for l == L-1
        float rn = rv;
        if (l < L - 1) {
            const float bv2 = blay[m * L + l + 1];
            const float av2 = 0.9409f + bv2 * (2.0947f + bv2 * (-0.8206f + bv2 * (0.2683f + bv2 * (-0.0251f))));
            rn = av2 * (1.6612f + av2 * (-0.4721f + av2 * (0.0671f + av2 * (-0.0043f + av2 * 0.000106f))));
        }
        const float rr  = rv / rn;
        const float xka = om / av;
        const float xkb = om / bv;
        const float t   = bv * iom;
        const float dm  = dlay[m * L + l];
        sA[l] = make_float4(dm, 2.0f * t * t, xka * xka, xkb * xkb);
        sB[l] = make_float4(rr, rr * rr, -NEG2LOG2E * dm, bv);
        if (l == 0) sIr0 = 1.0f / rv;
    }
    for (int k = tid; k < NC; k += blockDim.x) sIC[k] = 1.0f / Clist[k];
    __syncthreads();

    const float ir0 = sIr0;
    const float wve = om / vml;

    float mn =  3.4e38f;
    float mx = -3.4e38f;
    const unsigned full = 0xffffffffu;

    for (int k0 = 0; k0 <= NC; k0 += 128) {
        const int kw = k0 + (tid & ~31);
        if (kw > NC) break;                      // warp-uniform exit
        const int kk = k0 + tid;
        const int k  = (kk < NC) ? kk : NC;      // clamp tail lanes to e00
        const float wv = (k < NC) ? (om * sIC[k]) : wve;
        const float det = dltar4_point(wv * wv, L, ir0, sA, sB);
        if (kk < NC) {
            mn = fminf(mn, det);
            mx = fmaxf(mx, det);
        } else if (kk == NC) {
            sh_e00 = det;
        }
    }

#pragma unroll
    for (int o = 16; o > 0; o >>= 1) {
        mn = fminf(mn, __shfl_xor_sync(full, mn, o));
        mx = fmaxf(mx, __shfl_xor_sync(full, mx, o));
    }
    if ((tid & 31) == 0) {
        red_mn[tid >> 5] = mn;
        red_mx[tid >> 5] = mx;
    }
    __syncthreads();

    if (tid == 0) {
        mn = fminf(fminf(red_mn[0], red_mn[1]), fminf(red_mn[2], red_mn[3]));
        mx = fmaxf(fmaxf(red_mx[0], red_mx[1]), fmaxf(red_mx[2], red_mx[3]));
        const float rng = mx - mn;
        const float val = sh_e00 / rng;
        // |0.1^|val| - 1| = 1 - 10^(-|val|)
        const float contrib = (1.0f - exp10f(-fabsf(val))) / (float)P;
        atomicAdd(&out[m], contrib);
    }

    // Regularizer (DAMP_HORIZONTAL = 0): once per m, by the p==0 block.
    if (p == 0 && tid == 32) {
        float s = 0.0f;
        for (int i = 0; i < L; ++i) {
            float v;
            if (i == 0)          v = sB[0].w - sB[1].w;
            else if (i == L - 1) v = sB[L - 1].w - sB[L - 2].w;
            else                 v = 2.0f * sB[i].w - sB[i - 1].w - sB[i + 1].w;
            s += fabsf(v);
        }
        atomicAdd(&out[m], s / (float)L);
    }
}

extern "C" void kernel_launch(void* const* d_in, const int* in_sizes, int n_in,
                              void* d_out, int out_size)
{
    const float* vlist = (const float*)d_in[0];
    const float* tlist = (const float*)d_in[1];
    const float* dlay  = (const float*)d_in[2];
    const float* blay  = (const float*)d_in[3];
    const float* Clist = (const float*)d_in[4];
    float* out = (float*)d_out;

    const int M  = out_size;          // 64
    const int P  = in_sizes[0] / M;   // 100
    const int L  = in_sizes[3] / M;   // 32
    const int NC = in_sizes[4];       // 400

    cudaMemsetAsync(out, 0, (size_t)M * sizeof(float));

    dim3 grid(P, M);
    forward_kernel<<<grid, 128>>>(vlist, tlist, dlay, blay, Clist, out,
                                  M, P, L, NC);
}

// round 15
// speedup vs baseline: 1.1982x; 1.0625x over previous
#include <cuda_runtime.h>
#include <math.h>

#define TWO_PI_F 6.28318530717958647692f
#define NEG2LOG2E 2.885390081777926814f   /* 2*log2(e) */

__device__ __forceinline__ float sqrt_approx(float x) {
    float r; asm("sqrt.approx.f32 %0, %1;" : "=f"(r) : "f"(x)); return r;
}
__device__ __forceinline__ float rcp_approx(float x) {
    float r; asm("rcp.approx.f32 %0, %1;" : "=f"(r) : "f"(x)); return r;
}
__device__ __forceinline__ float ex2_approx(float x) {
    float r; asm("ex2.approx.f32 %0, %1;" : "=f"(r) : "f"(x)); return r;
}

// ---------------------------------------------------------------------------
// One Haskell layer step in two exact telescoping bases:
//  (a) rho-similarity basis (e~ = e*diag(rho^s), s=(0,1,1,1,2)): rho-free
//      coefficients; entering a layer costs 4 ratio muls.
//  (b) radical-scaled P/Q vectors (P-vec by ra, Q-vec by rb): the layer
//      matrix picks up a uniform factor R = ra*rb that telescopes out of
//      e0/max|e|; kills both reciprocals and the w/x divisions.
// a0 is obtained as sqrt(selP*selQ) where selP = exp(-2*pex) (= 1 in the
// propagating case, facP otherwise) — replaces a whole ex2 chain since
// facP = exp(-2p) is already computed.
// The exact-equality case (wvno == xk) is absorbed by the +1e-30f eps.
// A = {dm, gammk, xka^2, xkb^2}; B = {rr, rr^2, -2*log2e*dm, b_layer}.
// Per-layer warp votes skip trig+selects when no lane is propagating.
// NORM every 3rd step: per-step amplification <= ~1.5e9, 3-step window
// <= ~3e27 << fp32 max; intermediate scales cancel in the final ratio.
// ---------------------------------------------------------------------------
template<bool NORM>
__device__ __forceinline__ void layer_step(
    float4 A, float4 B, float wv2, float tt,
    float& e0, float& e1, float& e2, float& e3, float& e4)
{
    const unsigned full = 0xffffffffu;
    const float dm = A.x;
    const float gk = A.y;

    // basis change from previous layer's rho to this layer's rho
    e1 *= B.x; e2 *= B.x; e3 *= B.x; e4 *= B.y;

    const float ra2 = (wv2 - A.z) + 1e-30f;
    const float rb2 = (wv2 - A.w) + 1e-30f;
    const float ra  = sqrt_approx(fabsf(ra2));
    const float rb  = sqrt_approx(fabsf(rb2));

    const float facP = ex2_approx(ra * B.z);   // exp(-2p)
    const float facQ = ex2_approx(rb * B.z);   // exp(-2q)
    const float ceP  = fmaf(0.5f, facP, 0.5f);
    const float seP  = fmaf(-0.5f, facP, 0.5f);
    const float ceQ  = fmaf(0.5f, facQ, 0.5f);
    const float seQ  = fmaf(-0.5f, facQ, 0.5f);

    // ---- P side (scaled by ra); selP = exp(-2*pex) ----
    float cpS, wS, xS, selP;
    if (__any_sync(full, ra2 < 0.0f)) {
        const float p = ra * dm;
        float sp, cp_;
        __sincosf(p, &sp, &cp_);
        const bool lt = ra2 < 0.0f;
        const float sel = lt ? sp : seP;
        wS   = sel;
        xS   = ra2 * sel;               // lt: ra2<0 gives -ra^2*sp exactly
        cpS  = ra * (lt ? cp_ : ceP);
        selP = lt ? 1.0f : facP;
    } else {
        wS   = seP;
        xS   = ra2 * seP;
        cpS  = ra * ceP;
        selP = facP;
    }

    // ---- Q side (scaled by rb); selQ = exp(-2*sex) ----
    float cqS, yS, zS, selQ;
    if (__any_sync(full, rb2 < 0.0f)) {
        const float q = rb * dm;
        float sq, cq_;
        __sincosf(q, &sq, &cq_);
        const bool lt = rb2 < 0.0f;
        const float sel = lt ? sq : seQ;
        yS   = sel;
        zS   = rb2 * sel;
        cqS  = rb * (lt ? cq_ : ceQ);
        selQ = lt ? 1.0f : facQ;
    } else {
        yS   = seQ;
        zS   = rb2 * seQ;
        cqS  = rb * ceQ;
        selQ = facQ;
    }

    // a0 in the scaled basis: sqrt(selP*selQ) * R, R = ra*rb
    const float a0R = sqrt_approx(selP * selQ) * (ra * rb);

    const float cpcq = cpS * cqS;
    const float cpy  = cpS * yS;
    const float cpz  = cpS * zS;
    const float cqw  = cqS * wS;
    const float cqx  = cqS * xS;
    const float xy   = xS * yS;
    const float xz   = xS * zS;
    const float wy   = wS * yS;
    const float wz   = wS * zS;

    // ---- _dnka, hat basis (rho-free), entries scaled uniformly by R ----
    const float gam   = gk * wv2;
    const float gamm1 = gam - 1.0f;
    const float twgm1 = gam + gamm1;
    const float gmgmk = gam * gk;
    const float gmgm1 = gam * gamm1;
    const float gm1sq = gamm1 * gamm1;
    const float a0pq  = a0R - cpcq;

    const float wvwy = wv2 * wy;
    const float gw   = gm1sq * wy;
    const float gxz  = gmgmk * xz;

    const float c00 = cpcq - 2.0f * gmgm1 * a0pq - gxz - gm1sq * wvwy;
    const float c01 = wv2 * cpy - cqx;
    const float c02 = -(twgm1 * a0pq + gk * xz + gamm1 * wvwy);
    const float c03 = cpz - wv2 * cqw;
    const float c04 = -(2.0f * wv2 * a0pq + xz + wv2 * wvwy);
    const float c10 = gmgmk * cpz - gm1sq * cqw;
    const float c11 = cpcq;
    const float c12 = gk * cpz - gamm1 * cqw;
    const float c13 = -wz;
    const float c30 = gm1sq * cpy - gmgmk * cqx;
    const float c31 = -xy;
    const float c32 = gamm1 * cpy - gk * cqx;
    const float c40 = -(2.0f * gmgmk * gm1sq * a0pq + gmgmk * gxz + gm1sq * gw);
    const float c42 = -(gk * gamm1 * twgm1 * a0pq + gk * gxz + gamm1 * gw);
    const float c22 = a0R + 2.0f * (cpcq - c00);

    // e2t folds tt = -2*wvno2 into e2, replacing c20/c21/c23/c24 entirely.
    const float e2t = tt * e2;

    const float ee0 = e0 * c00 + e1 * c10 + e2t * c42 + e3 * c30 + e4 * c40;
    const float ee1 = e0 * c01 + e1 * c11 + e2t * c32 + e3 * c31 + e4 * c30;
    const float ee2 = e0 * c02 + e1 * c12 + e2  * c22 + e3 * c32 + e4 * c42;
    const float ee3 = e0 * c03 + e1 * c13 + e2t * c12 + e3 * c11 + e4 * c10;
    const float ee4 = e0 * c04 + e1 * c03 + e2t * c02 + e3 * c01 + e4 * c00;

    if (NORM) {
        // overflow-control scaling only (value cancels in the telescoping)
        float t1 = fmaxf(fabsf(ee0),
                   fmaxf(fabsf(ee1),
                   fmaxf(fabsf(ee2),
                   fmaxf(fabsf(ee3), fabsf(ee4)))));
        t1 = fmaxf(t1, 1e-30f);
        const float s = rcp_approx(t1);
        e0 = ee0 * s; e1 = ee1 * s; e2 = ee2 * s; e3 = ee3 * s; e4 = ee4 * s;
    } else {
        e0 = ee0; e1 = ee1; e2 = ee2; e3 = ee3; e4 = ee4;
    }
}

__device__ __forceinline__ float dltar4_point(
    float wv2, int L, float ir0,
    const float4* __restrict__ sA, const float4* __restrict__ sB)
{
    float e0, e1, e2, e3, e4;
    {
        // Halfspace init, hat basis of layer L-1 (overall r^2 scale dropped).
        const float4 A = sA[L - 1];
        const float ra = sqrt_approx(fabsf(wv2 - A.z));
        const float rb = sqrt_approx(fabsf(wv2 - A.w));
        const float gam = A.y * wv2;
        const float gamm1 = gam - 1.0f;
        const float rarb = ra * rb;
        e0 = gamm1 * gamm1 - gam * A.y * rarb;
        e1 = -ra;
        e2 = gamm1 - A.y * rarb;
        e3 = rb;
        e4 = wv2 - rarb;
    }
    const float tt = -2.0f * wv2;

    // Steps il = L-2 .. 0. Triples (norm, plain, plain); tail normalizes.
    const float4* Ap = sA + (L - 2);
    const float4* Bp = sB + (L - 2);
    int il = L - 2;
#pragma unroll 1
    for (; il > 2; il -= 3) {
        layer_step<true >(Ap[0],  Bp[0],  wv2, tt, e0, e1, e2, e3, e4);
        layer_step<false>(Ap[-1], Bp[-1], wv2, tt, e0, e1, e2, e3, e4);
        layer_step<false>(Ap[-2], Bp[-2], wv2, tt, e0, e1, e2, e3, e4);
        Ap -= 3; Bp -= 3;
    }
#pragma unroll 1
    for (; il >= 0; --il) {
        layer_step<true>(Ap[0], Bp[0], wv2, tt, e0, e1, e2, e3, e4);
        Ap -= 1; Bp -= 1;
    }

    // Convert back to the true basis (D_0^-1) and apply the reference's final
    // normalization; only e0/t1 is needed.
    e1 *= ir0; e2 *= ir0; e3 *= ir0; e4 *= ir0 * ir0;
    float t1 = fmaxf(fabsf(e0),
               fmaxf(fabsf(e1),
               fmaxf(fabsf(e2),
               fmaxf(fabsf(e3), fabsf(e4)))));
    if (t1 < 1e-30f) t1 = 1.0f;
    return e0 * rcp_approx(t1);
}

// ---------------------------------------------------------------------------
// One block per (m, p); 128 threads over 401 items (NC grid dets + e00 det).
// Warp-uniform pass break + clamped tail lanes: every executing warp has all
// 32 lanes active (full-mask votes legal); 13 warp-passes per block.
// ---------------------------------------------------------------------------
__global__ void __launch_bounds__(128, 8)
forward_kernel(const float* __restrict__ vlist, const float* __restrict__ tlist,
               const float* __restrict__ dlay, const float* __restrict__ blay,
               const float* __restrict__ Clist, float* __restrict__ out,
               int M, int P, int L, int NC)
{
    __shared__ float  sU[1024];   // 1/c^2
    __shared__ float4 sA[64];     // dm, gk, ka2, kb2
    __shared__ float4 sB[64];     // rr, rr^2, -2log2e*dm, b_l
    __shared__ float  red_mn[4], red_mx[4], sh_e00, sIr0;

    const int m   = blockIdx.y;
    const int p   = blockIdx.x;
    const int tid = threadIdx.x;

    const float om  = fmaxf(TWO_PI_F / tlist[m * P + p], 1e-4f);
    const float iom = 1.0f / om;
    const float om2 = om * om;
    const float vml = vlist[m * P + p];

    for (int l = tid; l < L; l += blockDim.x) {
        const float bv = blay[m * L + l];
        const float av = 0.9409f + bv * (2.0947f + bv * (-0.8206f + bv * (0.2683f + bv * (-0.0251f))));
        const float rv = av * (1.6612f + av * (-0.4721f + av * (0.0671f + av * (-0.0043f + av * 0.000106f))));
        // rho of layer l+1 (for the basis ratio); dummy for l == L-1
        float rn = rv;
        if (l < L - 1) {
            const float bv2 = blay[m * L + l + 1];
            const float av2 = 0.9409f + bv2 * (2.0947f + bv2 * (-0.8206f + bv2 * (0.2683f + bv2 * (-0.0251f))));
            rn = av2 * (1.6612f + av2 * (-0.4721f + av2 * (0.0671f + av2 * (-0.0043f + av2 * 0.000106f))));
        }
        const float rr  = rv / rn;
        const float xka = om / av;
        const float xkb = om / bv;
        const float t   = bv * iom;
        const float dm  = dlay[m * L + l];
        sA[l] = make_float4(dm, 2.0f * t * t, xka * xka, xkb * xkb);
        sB[l] = make_float4(rr, rr * rr, -NEG2LOG2E * dm, bv);
        if (l == 0) sIr0 = 1.0f / rv;
    }
    for (int k = tid; k < NC; k += blockDim.x) {
        const float ic = 1.0f / Clist[k];
        sU[k] = ic * ic;
    }
    __syncthreads();

    const float ir0 = sIr0;
    const float ivm = 1.0f / vml;
    const float ue  = ivm * ivm;   // e00 point: u = 1/v^2

    float mn =  3.4e38f;
    float mx = -3.4e38f;
    const unsigned full = 0xffffffffu;

    for (int k0 = 0; k0 <= NC; k0 += 128) {
        const int kw = k0 + (tid & ~31);
        if (kw > NC) break;                      // warp-uniform exit
        const int kk = k0 + tid;
        const int k  = (kk < NC) ? kk : NC;      // clamp tail lanes to e00
        const float u = (k < NC) ? sU[k] : ue;
        const float det = dltar4_point(om2 * u, L, ir0, sA, sB);
        if (kk < NC) {
            mn = fminf(mn, det);
            mx = fmaxf(mx, det);
        } else if (kk == NC) {
            sh_e00 = det;
        }
    }

#pragma unroll
    for (int o = 16; o > 0; o >>= 1) {
        mn = fminf(mn, __shfl_xor_sync(full, mn, o));
        mx = fmaxf(mx, __shfl_xor_sync(full, mx, o));
    }
    if ((tid & 31) == 0) {
        red_mn[tid >> 5] = mn;
        red_mx[tid >> 5] = mx;
    }
    __syncthreads();

    if (tid == 0) {
        mn = fminf(fminf(red_mn[0], red_mn[1]), fminf(red_mn[2], red_mn[3]));
        mx = fmaxf(fmaxf(red_mx[0], red_mx[1]), fmaxf(red_mx[2], red_mx[3]));
        const float rng = mx - mn;
        const float val = sh_e00 / rng;
        // |0.1^|val| - 1| = 1 - 10^(-|val|)
        const float contrib = (1.0f - exp10f(-fabsf(val))) / (float)P;
        atomicAdd(&out[m], contrib);
    }

    // Regularizer (DAMP_HORIZONTAL = 0): once per m, by the p==0 block.
    if (p == 0 && tid == 32) {
        float s = 0.0f;
        for (int i = 0; i < L; ++i) {
            float v;
            if (i == 0)          v = sB[0].w - sB[1].w;
            else if (i == L - 1) v = sB[L - 1].w - sB[L - 2].w;
            else                 v = 2.0f * sB[i].w - sB[i - 1].w - sB[i + 1].w;
            s += fabsf(v);
        }
        atomicAdd(&out[m], s / (float)L);
    }
}

extern "C" void kernel_launch(void* const* d_in, const int* in_sizes, int n_in,
                              void* d_out, int out_size)
{
    const float* vlist = (const float*)d_in[0];
    const float* tlist = (const float*)d_in[1];
    const float* dlay  = (const float*)d_in[2];
    const float* blay  = (const float*)d_in[3];
    const float* Clist = (const float*)d_in[4];
    float* out = (float*)d_out;

    const int M  = out_size;          // 64
    const int P  = in_sizes[0] / M;   // 100
    const int L  = in_sizes[3] / M;   // 32
    const int NC = in_sizes[4];       // 400

    cudaMemsetAsync(out, 0, (size_t)M * sizeof(float));

    dim3 grid(P, M);
    forward_kernel<<<grid, 128>>>(vlist, tlist, dlay, blay, Clist, out,
                                  M, P, L, NC);
}